// round 1
// baseline (speedup 1.0000x reference)
#include <cuda_runtime.h>
#include <math.h>
#include <stdint.h>

// ---------------- problem constants ----------------
static constexpr int NUSERS = 100000;
static constexpr int NITEMS = 50000;
static constexpr int NNODE  = 150000;       // NUSERS + NITEMS
static constexpr int NEDGE  = 1200000;      // 2 * 600000
static constexpr int DIM    = 64;

// ---------------- device scratch (static; no runtime alloc) ----------------
__device__ float g_edge_w[NEDGE];
__device__ float g_csrw[NEDGE];
__device__ int   g_src[NEDGE];
__device__ float g_wdeg[NNODE];
__device__ float g_dinv[NNODE];
__device__ int   g_cnt[NNODE];
__device__ int   g_rowptr[NNODE + 1];
__device__ int   g_cursor[NNODE];
__device__ float g_xA[(size_t)NNODE * DIM];
__device__ float g_xB[(size_t)NNODE * DIM];
__device__ float g_acc[(size_t)NNODE * DIM];

// ---------------- kernels ----------------

__global__ void zero_kernel() {
    int i = blockIdx.x * blockDim.x + threadIdx.x;
    if (i < NNODE) { g_wdeg[i] = 0.f; g_cnt[i] = 0; }
}

// edge gate MLP: sigmoid(relu(f @ W1 + b1) @ w2 + b2); also histogram weighted degree + count
__global__ void mlp_kernel(const float* __restrict__ ef,
                           const float* __restrict__ w1,
                           const float* __restrict__ b1,
                           const float* __restrict__ w2,
                           const float* __restrict__ b2,
                           const int*   __restrict__ eidx) {
    __shared__ float sW1[8 * 32];
    __shared__ float sB1[32];
    __shared__ float sW2[32];
    __shared__ float sB2;
    int t = threadIdx.x;
    if (t < 256) sW1[t] = w1[t];
    if (t < 32)  { sB1[t] = b1[t]; sW2[t] = w2[t]; }
    if (t == 0)  sB2 = b2[0];
    __syncthreads();

    int e = blockIdx.x * blockDim.x + t;
    if (e >= NEDGE) return;

    const float4* fp = reinterpret_cast<const float4*>(ef + (size_t)e * 8);
    float4 fa = fp[0];
    float4 fb = fp[1];
    float f[8] = {fa.x, fa.y, fa.z, fa.w, fb.x, fb.y, fb.z, fb.w};

    float out = sB2;
    #pragma unroll
    for (int j = 0; j < 32; j++) {
        float h = sB1[j];
        #pragma unroll
        for (int i = 0; i < 8; i++) h = fmaf(f[i], sW1[i * 32 + j], h);
        h = fmaxf(h, 0.f);
        out = fmaf(h, sW2[j], out);
    }
    float w = 1.f / (1.f + expf(-out));

    g_edge_w[e] = w;
    int c = eidx[NEDGE + e];          // edge_index[1][e]
    atomicAdd(&g_wdeg[c], w);
    atomicAdd(&g_cnt[c], 1);
}

// single-block exclusive scan of g_cnt -> g_rowptr/g_cursor; also dinv
__global__ void scan_kernel() {
    constexpr int CH = (NNODE + 1023) / 1024;   // 147
    int t  = threadIdx.x;
    int lo = t * CH;
    int hi = min(lo + CH, NNODE);

    int s = 0;
    for (int n = lo; n < hi; n++) s += g_cnt[n];

    __shared__ int part[1024];
    part[t] = s;
    __syncthreads();
    for (int off = 1; off < 1024; off <<= 1) {
        int v = (t >= off) ? part[t - off] : 0;
        __syncthreads();
        part[t] += v;
        __syncthreads();
    }
    int run = part[t] - s;   // exclusive prefix

    for (int n = lo; n < hi; n++) {
        g_rowptr[n] = run;
        g_cursor[n] = run;
        run += g_cnt[n];
        float dg = g_wdeg[n];
        g_dinv[n] = (dg > 0.f) ? rsqrtf(dg) : 0.f;
    }
    if (t == 0) g_rowptr[NNODE] = NEDGE;
}

// bucket edges by destination (counting-sort scatter); store pre-normalized weight
__global__ void scatter_kernel(const int* __restrict__ eidx) {
    int e = blockIdx.x * blockDim.x + threadIdx.x;
    if (e >= NEDGE) return;
    int r = eidx[e];
    int c = eidx[NEDGE + e];
    float w = g_dinv[r] * g_edge_w[e] * g_dinv[c];
    int p = atomicAdd(&g_cursor[c], 1);
    g_src[p]  = r;
    g_csrw[p] = w;
}

// x0 = [ l2norm(user_emb) ; l2norm(0.3*audio + 0.44*(artist+album)) ]; acc = x0
__global__ void init_kernel(const float* __restrict__ uemb,
                            const float* __restrict__ audio,
                            const float* __restrict__ art,
                            const float* __restrict__ alb,
                            const int*   __restrict__ aid,
                            const int*   __restrict__ bid) {
    int warp = (blockIdx.x * blockDim.x + threadIdx.x) >> 5;
    int lane = threadIdx.x & 31;
    if (warp >= NNODE) return;

    float v0, v1;
    if (warp < NUSERS) {
        const float* p = uemb + (size_t)warp * DIM;
        v0 = p[lane];
        v1 = p[lane + 32];
    } else {
        int i = warp - NUSERS;
        int a = aid[i];
        int b = bid[i];
        const float* pa = audio + (size_t)i * DIM;
        const float* pr = art   + (size_t)a * DIM;
        const float* pl = alb   + (size_t)b * DIM;
        v0 = pa[lane]      * 0.3f + (pr[lane]      + pl[lane])      * 0.44f;
        v1 = pa[lane + 32] * 0.3f + (pr[lane + 32] + pl[lane + 32]) * 0.44f;
    }
    float ss = v0 * v0 + v1 * v1;
    #pragma unroll
    for (int o = 16; o > 0; o >>= 1) ss += __shfl_xor_sync(0xffffffffu, ss, o);
    float inv = 1.f / fmaxf(sqrtf(ss), 1e-12f);
    v0 *= inv; v1 *= inv;

    size_t base = (size_t)warp * DIM;
    g_xA[base + lane] = v0;  g_xA[base + lane + 32] = v1;
    g_acc[base + lane] = v0; g_acc[base + lane + 32] = v1;
}

// one propagation layer: x_out[n] = sum_{e in CSR[n]} w_e * x_in[src_e]; acc += x_out
__global__ void gather_kernel(int ping) {
    const float* __restrict__ xin  = ping ? g_xB : g_xA;
    float*       __restrict__ xout = ping ? g_xA : g_xB;

    int warp = (blockIdx.x * blockDim.x + threadIdx.x) >> 5;
    int lane = threadIdx.x & 31;
    if (warp >= NNODE) return;

    int beg = g_rowptr[warp];
    int end = g_rowptr[warp + 1];
    float a0 = 0.f, a1 = 0.f;
    for (int e = beg; e < end; e++) {
        int   s = __ldg(&g_src[e]);
        float w = __ldg(&g_csrw[e]);
        const float* p = xin + (size_t)s * DIM;
        a0 = fmaf(w, __ldg(p + lane),      a0);
        a1 = fmaf(w, __ldg(p + lane + 32), a1);
    }
    size_t base = (size_t)warp * DIM;
    xout[base + lane]      = a0;
    xout[base + lane + 32] = a1;
    g_acc[base + lane]      += a0;
    g_acc[base + lane + 32] += a1;
}

// out = l2norm(acc / 4); trailing scalar align_loss = 0
__global__ void final_kernel(float* __restrict__ out) {
    int warp = (blockIdx.x * blockDim.x + threadIdx.x) >> 5;
    int lane = threadIdx.x & 31;
    if (warp >= NNODE) return;

    size_t base = (size_t)warp * DIM;
    float v0 = g_acc[base + lane]      * 0.25f;
    float v1 = g_acc[base + lane + 32] * 0.25f;
    float ss = v0 * v0 + v1 * v1;
    #pragma unroll
    for (int o = 16; o > 0; o >>= 1) ss += __shfl_xor_sync(0xffffffffu, ss, o);
    float inv = 1.f / fmaxf(sqrtf(ss), 1e-12f);
    out[base + lane]      = v0 * inv;
    out[base + lane + 32] = v1 * inv;

    if (blockIdx.x == 0 && threadIdx.x == 0) out[(size_t)NNODE * DIM] = 0.f;
}

// ---------------- launcher ----------------
extern "C" void kernel_launch(void* const* d_in, const int* in_sizes, int n_in,
                              void* d_out, int out_size) {
    const float* uemb  = (const float*)d_in[0];   // user_emb_w      [100000,64]
    const float* audio = (const float*)d_in[1];   // item_audio_emb  [50000,64]
    const float* art   = (const float*)d_in[2];   // artist_emb_w    [20000,64]
    const float* alb   = (const float*)d_in[3];   // album_emb_w     [40000,64]
    const float* w1    = (const float*)d_in[4];   // mlp_w1 [8,32]
    const float* b1    = (const float*)d_in[5];   // mlp_b1 [32]
    const float* w2    = (const float*)d_in[6];   // mlp_w2 [32,1]
    const float* b2    = (const float*)d_in[7];   // mlp_b2 [1]
    const float* ef    = (const float*)d_in[8];   // edge_features [E,8]
    const int*   eidx  = (const int*)  d_in[9];   // edge_index [2,E]
    const int*   aid   = (const int*)  d_in[10];  // artist_ids [50000]
    const int*   bid   = (const int*)  d_in[11];  // album_ids  [50000]
    float* out = (float*)d_out;

    const int edgeBlocks = (NEDGE + 255) / 256;
    const int nodeBlocks = (NNODE + 255) / 256;
    const int warpBlocks = (NNODE * 32 + 255) / 256;   // one warp per node

    zero_kernel   <<<nodeBlocks, 256>>>();
    mlp_kernel    <<<edgeBlocks, 256>>>(ef, w1, b1, w2, b2, eidx);
    scan_kernel   <<<1, 1024>>>();
    scatter_kernel<<<edgeBlocks, 256>>>(eidx);
    init_kernel   <<<warpBlocks, 256>>>(uemb, audio, art, alb, aid, bid);
    gather_kernel <<<warpBlocks, 256>>>(0);   // xA -> xB
    gather_kernel <<<warpBlocks, 256>>>(1);   // xB -> xA
    gather_kernel <<<warpBlocks, 256>>>(0);   // xA -> xB
    final_kernel  <<<warpBlocks, 256>>>(out);
}

// round 2
// speedup vs baseline: 1.0484x; 1.0484x over previous
#include <cuda_runtime.h>
#include <math.h>
#include <stdint.h>

// ---------------- problem constants ----------------
static constexpr int NUSERS = 100000;
static constexpr int NITEMS = 50000;
static constexpr int NNODE  = 150000;       // NUSERS + NITEMS
static constexpr int NEDGE  = 1200000;      // 2 * 600000
static constexpr int DIM    = 64;

// ---------------- device scratch (static; no runtime alloc) ----------------
__device__ float g_edge_w[NEDGE];
__device__ int2  g_edge[NEDGE];             // {src, __float_as_int(norm_w)}
__device__ float g_wdeg[NNODE];
__device__ float g_dinv[NNODE];
__device__ int   g_cnt[NNODE];
__device__ int   g_rowptr[NNODE + 1];
__device__ int   g_cursor[NNODE];
__device__ float g_xA[(size_t)NNODE * DIM];
__device__ float g_xB[(size_t)NNODE * DIM];
__device__ float g_acc[(size_t)NNODE * DIM];

// ---------------- kernels ----------------

__global__ void zero_kernel() {
    int i = blockIdx.x * blockDim.x + threadIdx.x;
    if (i < NNODE) { g_wdeg[i] = 0.f; g_cnt[i] = 0; }
}

// edge gate MLP: sigmoid(relu(f @ W1 + b1) @ w2 + b2); also histogram weighted degree + count
__global__ void mlp_kernel(const float* __restrict__ ef,
                           const float* __restrict__ w1,
                           const float* __restrict__ b1,
                           const float* __restrict__ w2,
                           const float* __restrict__ b2,
                           const int*   __restrict__ eidx) {
    __shared__ float sW1[8 * 32];
    __shared__ float sB1[32];
    __shared__ float sW2[32];
    __shared__ float sB2;
    int t = threadIdx.x;
    if (t < 256) sW1[t] = w1[t];
    if (t < 32)  { sB1[t] = b1[t]; sW2[t] = w2[t]; }
    if (t == 0)  sB2 = b2[0];
    __syncthreads();

    int e = blockIdx.x * blockDim.x + t;
    if (e >= NEDGE) return;

    const float4* fp = reinterpret_cast<const float4*>(ef + (size_t)e * 8);
    float4 fa = fp[0];
    float4 fb = fp[1];
    float f[8] = {fa.x, fa.y, fa.z, fa.w, fb.x, fb.y, fb.z, fb.w};

    float out = sB2;
    #pragma unroll
    for (int j = 0; j < 32; j++) {
        float h = sB1[j];
        #pragma unroll
        for (int i = 0; i < 8; i++) h = fmaf(f[i], sW1[i * 32 + j], h);
        h = fmaxf(h, 0.f);
        out = fmaf(h, sW2[j], out);
    }
    float w = 1.f / (1.f + expf(-out));

    g_edge_w[e] = w;
    int c = eidx[NEDGE + e];          // edge_index[1][e]
    atomicAdd(&g_wdeg[c], w);
    atomicAdd(&g_cnt[c], 1);
}

// single-block exclusive scan of g_cnt -> g_rowptr/g_cursor; also dinv
__global__ void scan_kernel() {
    constexpr int CH = (NNODE + 1023) / 1024;   // 147
    int t  = threadIdx.x;
    int lo = t * CH;
    int hi = min(lo + CH, NNODE);

    int s = 0;
    for (int n = lo; n < hi; n++) s += g_cnt[n];

    __shared__ int part[1024];
    part[t] = s;
    __syncthreads();
    for (int off = 1; off < 1024; off <<= 1) {
        int v = (t >= off) ? part[t - off] : 0;
        __syncthreads();
        part[t] += v;
        __syncthreads();
    }
    int run = part[t] - s;   // exclusive prefix

    for (int n = lo; n < hi; n++) {
        g_rowptr[n] = run;
        g_cursor[n] = run;
        run += g_cnt[n];
        float dg = g_wdeg[n];
        g_dinv[n] = (dg > 0.f) ? rsqrtf(dg) : 0.f;
    }
    if (t == 0) g_rowptr[NNODE] = NEDGE;
}

// bucket edges by destination (counting-sort scatter); store {src, pre-normalized weight}
__global__ void scatter_kernel(const int* __restrict__ eidx) {
    int e = blockIdx.x * blockDim.x + threadIdx.x;
    if (e >= NEDGE) return;
    int r = eidx[e];
    int c = eidx[NEDGE + e];
    float w = g_dinv[r] * g_edge_w[e] * g_dinv[c];
    int p = atomicAdd(&g_cursor[c], 1);
    g_edge[p] = make_int2(r, __float_as_int(w));
}

// x0 = [ l2norm(user_emb) ; l2norm(0.3*audio + 0.44*(artist+album)) ]; acc = x0
// 16 lanes per node, float4 per lane.
__global__ void __launch_bounds__(256) init_kernel(const float* __restrict__ uemb,
                            const float* __restrict__ audio,
                            const float* __restrict__ art,
                            const float* __restrict__ alb,
                            const int*   __restrict__ aid,
                            const int*   __restrict__ bid) {
    int t = blockIdx.x * blockDim.x + threadIdx.x;
    int node = t >> 4;
    int sub  = t & 15;
    if (node >= NNODE) return;

    float4 v;
    if (node < NUSERS) {
        v = __ldg(reinterpret_cast<const float4*>(uemb) + (size_t)node * 16 + sub);
    } else {
        int i = node - NUSERS;
        int a = __ldg(&aid[i]);
        int b = __ldg(&bid[i]);
        float4 pa = __ldg(reinterpret_cast<const float4*>(audio) + (size_t)i * 16 + sub);
        float4 pr = __ldg(reinterpret_cast<const float4*>(art)   + (size_t)a * 16 + sub);
        float4 pl = __ldg(reinterpret_cast<const float4*>(alb)   + (size_t)b * 16 + sub);
        v.x = pa.x * 0.3f + (pr.x + pl.x) * 0.44f;
        v.y = pa.y * 0.3f + (pr.y + pl.y) * 0.44f;
        v.z = pa.z * 0.3f + (pr.z + pl.z) * 0.44f;
        v.w = pa.w * 0.3f + (pr.w + pl.w) * 0.44f;
    }
    float ss = v.x * v.x + v.y * v.y + v.z * v.z + v.w * v.w;
    #pragma unroll
    for (int o = 8; o > 0; o >>= 1) ss += __shfl_xor_sync(0xffffffffu, ss, o);
    float inv = 1.f / fmaxf(sqrtf(ss), 1e-12f);
    v.x *= inv; v.y *= inv; v.z *= inv; v.w *= inv;

    size_t o = (size_t)node * 16 + sub;
    reinterpret_cast<float4*>(g_xA)[o]  = v;
    reinterpret_cast<float4*>(g_acc)[o] = v;
}

// one propagation layer: x_out[n] = sum_{e in CSR[n]} w_e * x_in[src_e]; acc += x_out
// warp = 1 node; each iteration handles 2 edges (one per half-warp), float4 per lane.
__global__ void __launch_bounds__(256) gather_kernel(int ping, int last) {
    const float4* __restrict__ xin  = reinterpret_cast<const float4*>(ping ? g_xB : g_xA);
    float4*       __restrict__ xout = reinterpret_cast<float4*>(ping ? g_xA : g_xB);

    int warp = (blockIdx.x * blockDim.x + threadIdx.x) >> 5;
    int lane = threadIdx.x & 31;
    if (warp >= NNODE) return;
    int sub = lane & 15;
    int hi  = lane >> 4;

    int beg = g_rowptr[warp];
    int end = g_rowptr[warp + 1];

    float4 a = make_float4(0.f, 0.f, 0.f, 0.f);
    #pragma unroll 4
    for (int e = beg; e < end; e += 2) {
        int ee = e + hi;
        if (ee < end) {
            int2 m = __ldg(&g_edge[ee]);
            float w = __int_as_float(m.y);
            float4 v = __ldg(xin + (size_t)m.x * 16 + sub);
            a.x = fmaf(w, v.x, a.x);
            a.y = fmaf(w, v.y, a.y);
            a.z = fmaf(w, v.z, a.z);
            a.w = fmaf(w, v.w, a.w);
        }
    }
    // cross-half reduction: both halves end with the full sum
    a.x += __shfl_xor_sync(0xffffffffu, a.x, 16);
    a.y += __shfl_xor_sync(0xffffffffu, a.y, 16);
    a.z += __shfl_xor_sync(0xffffffffu, a.z, 16);
    a.w += __shfl_xor_sync(0xffffffffu, a.w, 16);

    size_t o = (size_t)warp * 16 + sub;
    if (hi) {
        // lanes 16-31: acc RMW
        float4* accp = reinterpret_cast<float4*>(g_acc);
        float4 c = accp[o];
        c.x += a.x; c.y += a.y; c.z += a.z; c.w += a.w;
        accp[o] = c;
    } else if (!last) {
        // lanes 0-15: next-layer x store (dead on last layer)
        xout[o] = a;
    }
}

// out = l2norm(acc / 4); trailing scalar align_loss = 0
__global__ void __launch_bounds__(256) final_kernel(float* __restrict__ out) {
    int t = blockIdx.x * blockDim.x + threadIdx.x;
    int node = t >> 4;
    int sub  = t & 15;
    if (node >= NNODE) return;

    size_t o = (size_t)node * 16 + sub;
    float4 v = reinterpret_cast<const float4*>(g_acc)[o];
    v.x *= 0.25f; v.y *= 0.25f; v.z *= 0.25f; v.w *= 0.25f;
    float ss = v.x * v.x + v.y * v.y + v.z * v.z + v.w * v.w;
    #pragma unroll
    for (int oo = 8; oo > 0; oo >>= 1) ss += __shfl_xor_sync(0xffffffffu, ss, oo);
    float inv = 1.f / fmaxf(sqrtf(ss), 1e-12f);
    v.x *= inv; v.y *= inv; v.z *= inv; v.w *= inv;
    reinterpret_cast<float4*>(out)[o] = v;

    if (blockIdx.x == 0 && threadIdx.x == 0) out[(size_t)NNODE * DIM] = 0.f;
}

// ---------------- launcher ----------------
extern "C" void kernel_launch(void* const* d_in, const int* in_sizes, int n_in,
                              void* d_out, int out_size) {
    const float* uemb  = (const float*)d_in[0];   // user_emb_w      [100000,64]
    const float* audio = (const float*)d_in[1];   // item_audio_emb  [50000,64]
    const float* art   = (const float*)d_in[2];   // artist_emb_w    [20000,64]
    const float* alb   = (const float*)d_in[3];   // album_emb_w     [40000,64]
    const float* w1    = (const float*)d_in[4];   // mlp_w1 [8,32]
    const float* b1    = (const float*)d_in[5];   // mlp_b1 [32]
    const float* w2    = (const float*)d_in[6];   // mlp_w2 [32,1]
    const float* b2    = (const float*)d_in[7];   // mlp_b2 [1]
    const float* ef    = (const float*)d_in[8];   // edge_features [E,8]
    const int*   eidx  = (const int*)  d_in[9];   // edge_index [2,E]
    const int*   aid   = (const int*)  d_in[10];  // artist_ids [50000]
    const int*   bid   = (const int*)  d_in[11];  // album_ids  [50000]
    float* out = (float*)d_out;

    const int edgeBlocks = (NEDGE + 255) / 256;
    const int nodeBlocks = (NNODE + 255) / 256;
    const int warpBlocks = (NNODE * 32 + 255) / 256;   // one warp per node
    const int vecBlocks  = (NNODE * 16 + 255) / 256;   // 16 lanes per node

    zero_kernel   <<<nodeBlocks, 256>>>();
    mlp_kernel    <<<edgeBlocks, 256>>>(ef, w1, b1, w2, b2, eidx);
    scan_kernel   <<<1, 1024>>>();
    scatter_kernel<<<edgeBlocks, 256>>>(eidx);
    init_kernel   <<<vecBlocks, 256>>>(uemb, audio, art, alb, aid, bid);
    gather_kernel <<<warpBlocks, 256>>>(0, 0);   // xA -> xB
    gather_kernel <<<warpBlocks, 256>>>(1, 0);   // xB -> xA
    gather_kernel <<<warpBlocks, 256>>>(0, 1);   // xA -> (acc only)
    final_kernel  <<<vecBlocks, 256>>>(out);
}

// round 3
// speedup vs baseline: 1.0863x; 1.0362x over previous
#include <cuda_runtime.h>
#include <cuda_fp16.h>
#include <math.h>
#include <stdint.h>

// ---------------- problem constants ----------------
static constexpr int NUSERS = 100000;
static constexpr int NITEMS = 50000;
static constexpr int NNODE  = 150000;       // NUSERS + NITEMS
static constexpr int NEDGE  = 1200000;      // 2 * 600000
static constexpr int DIM    = 64;

// ---------------- device scratch (static; no runtime alloc) ----------------
__device__ float  g_edge_w[NEDGE];
__device__ int2   g_edge[NEDGE];            // {src, __float_as_int(norm_w)}
__device__ float  g_wdeg[NNODE];
__device__ float  g_dinv[NNODE];
__device__ int    g_cnt[NNODE];
__device__ int    g_rowptr[NNODE + 1];
__device__ int    g_cursor[NNODE];
__device__ __half g_hA[(size_t)NNODE * DIM];   // fp16 x ping
__device__ __half g_hB[(size_t)NNODE * DIM];   // fp16 x pong
__device__ float  g_acc[(size_t)NNODE * DIM];  // fp32 accumulator

// ---------------- kernels ----------------

__global__ void zero_kernel() {
    int i = blockIdx.x * blockDim.x + threadIdx.x;
    if (i < NNODE) { g_wdeg[i] = 0.f; g_cnt[i] = 0; }
}

// edge gate MLP: sigmoid(relu(f @ W1 + b1) @ w2 + b2); also histogram weighted degree + count
__global__ void mlp_kernel(const float* __restrict__ ef,
                           const float* __restrict__ w1,
                           const float* __restrict__ b1,
                           const float* __restrict__ w2,
                           const float* __restrict__ b2,
                           const int*   __restrict__ eidx) {
    __shared__ float sW1[8 * 32];
    __shared__ float sB1[32];
    __shared__ float sW2[32];
    __shared__ float sB2;
    int t = threadIdx.x;
    if (t < 256) sW1[t] = w1[t];
    if (t < 32)  { sB1[t] = b1[t]; sW2[t] = w2[t]; }
    if (t == 0)  sB2 = b2[0];
    __syncthreads();

    int e = blockIdx.x * blockDim.x + t;
    if (e >= NEDGE) return;

    const float4* fp = reinterpret_cast<const float4*>(ef + (size_t)e * 8);
    float4 fa = fp[0];
    float4 fb = fp[1];
    float f[8] = {fa.x, fa.y, fa.z, fa.w, fb.x, fb.y, fb.z, fb.w};

    float out = sB2;
    #pragma unroll
    for (int j = 0; j < 32; j++) {
        float h = sB1[j];
        #pragma unroll
        for (int i = 0; i < 8; i++) h = fmaf(f[i], sW1[i * 32 + j], h);
        h = fmaxf(h, 0.f);
        out = fmaf(h, sW2[j], out);
    }
    float w = 1.f / (1.f + expf(-out));

    g_edge_w[e] = w;
    int c = eidx[NEDGE + e];          // edge_index[1][e]
    atomicAdd(&g_wdeg[c], w);
    atomicAdd(&g_cnt[c], 1);
}

// single-block exclusive scan of g_cnt -> g_rowptr/g_cursor; also dinv
__global__ void scan_kernel() {
    constexpr int CH = (NNODE + 1023) / 1024;   // 147
    int t  = threadIdx.x;
    int lo = t * CH;
    int hi = min(lo + CH, NNODE);

    int s = 0;
    for (int n = lo; n < hi; n++) s += g_cnt[n];

    __shared__ int part[1024];
    part[t] = s;
    __syncthreads();
    for (int off = 1; off < 1024; off <<= 1) {
        int v = (t >= off) ? part[t - off] : 0;
        __syncthreads();
        part[t] += v;
        __syncthreads();
    }
    int run = part[t] - s;   // exclusive prefix

    for (int n = lo; n < hi; n++) {
        g_rowptr[n] = run;
        g_cursor[n] = run;
        run += g_cnt[n];
        float dg = g_wdeg[n];
        g_dinv[n] = (dg > 0.f) ? rsqrtf(dg) : 0.f;
    }
    if (t == 0) g_rowptr[NNODE] = NEDGE;
}

// bucket edges by destination (counting-sort scatter); store {src, pre-normalized weight}
__global__ void scatter_kernel(const int* __restrict__ eidx) {
    int e = blockIdx.x * blockDim.x + threadIdx.x;
    if (e >= NEDGE) return;
    int r = eidx[e];
    int c = eidx[NEDGE + e];
    float w = g_dinv[r] * g_edge_w[e] * g_dinv[c];
    int p = atomicAdd(&g_cursor[c], 1);
    g_edge[p] = make_int2(r, __float_as_int(w));
}

// x0 = [ l2norm(user_emb) ; l2norm(0.3*audio + 0.44*(artist+album)) ]
// acc(fp32) = x0 ; g_hA(fp16) = x0.   16 lanes per node, float4 per lane.
__global__ void __launch_bounds__(256) init_kernel(const float* __restrict__ uemb,
                            const float* __restrict__ audio,
                            const float* __restrict__ art,
                            const float* __restrict__ alb,
                            const int*   __restrict__ aid,
                            const int*   __restrict__ bid) {
    int t = blockIdx.x * blockDim.x + threadIdx.x;
    int node = t >> 4;
    int sub  = t & 15;
    if (node >= NNODE) return;

    float4 v;
    if (node < NUSERS) {
        v = __ldg(reinterpret_cast<const float4*>(uemb) + (size_t)node * 16 + sub);
    } else {
        int i = node - NUSERS;
        int a = __ldg(&aid[i]);
        int b = __ldg(&bid[i]);
        float4 pa = __ldg(reinterpret_cast<const float4*>(audio) + (size_t)i * 16 + sub);
        float4 pr = __ldg(reinterpret_cast<const float4*>(art)   + (size_t)a * 16 + sub);
        float4 pl = __ldg(reinterpret_cast<const float4*>(alb)   + (size_t)b * 16 + sub);
        v.x = pa.x * 0.3f + (pr.x + pl.x) * 0.44f;
        v.y = pa.y * 0.3f + (pr.y + pl.y) * 0.44f;
        v.z = pa.z * 0.3f + (pr.z + pl.z) * 0.44f;
        v.w = pa.w * 0.3f + (pr.w + pl.w) * 0.44f;
    }
    float ss = v.x * v.x + v.y * v.y + v.z * v.z + v.w * v.w;
    #pragma unroll
    for (int o = 8; o > 0; o >>= 1) ss += __shfl_xor_sync(0xffffffffu, ss, o);
    float inv = 1.f / fmaxf(sqrtf(ss), 1e-12f);
    v.x *= inv; v.y *= inv; v.z *= inv; v.w *= inv;

    size_t o = (size_t)node * 16 + sub;
    reinterpret_cast<float4*>(g_acc)[o] = v;

    // fp16 store: 4 halves = 8B per lane, row = 128B
    __half2 h0 = __floats2half2_rn(v.x, v.y);
    __half2 h1 = __floats2half2_rn(v.z, v.w);
    uint2 hv;
    hv.x = *reinterpret_cast<unsigned int*>(&h0);
    hv.y = *reinterpret_cast<unsigned int*>(&h1);
    reinterpret_cast<uint2*>(g_hA)[o] = hv;
}

// one propagation layer over fp16 x: warp = 1 node, 4 edges per iteration,
// 8 lanes per edge, each lane loads uint4 = 8 halves (row = 128B = 1 line).
__global__ void __launch_bounds__(256) gather_kernel(int ping, int last) {
    const uint4* __restrict__ xin  = reinterpret_cast<const uint4*>(ping ? g_hB : g_hA);
    uint4*       __restrict__ xout = reinterpret_cast<uint4*>(ping ? g_hA : g_hB);

    int warp = (blockIdx.x * blockDim.x + threadIdx.x) >> 5;
    int lane = threadIdx.x & 31;
    if (warp >= NNODE) return;
    int slot = lane >> 3;     // 0..3  : which edge of the group of 4
    int sub  = lane & 7;      // 0..7  : which 16B chunk of the 128B row

    int beg = g_rowptr[warp];
    int end = g_rowptr[warp + 1];

    float a[8] = {0.f, 0.f, 0.f, 0.f, 0.f, 0.f, 0.f, 0.f};
    for (int e = beg; e < end; e += 4) {
        int ee = e + slot;
        if (ee < end) {
            int2 m = __ldg(&g_edge[ee]);
            float w = __int_as_float(m.y);
            uint4 v = __ldg(xin + (size_t)m.x * 8 + sub);
            __half2 h0 = *reinterpret_cast<__half2*>(&v.x);
            __half2 h1 = *reinterpret_cast<__half2*>(&v.y);
            __half2 h2 = *reinterpret_cast<__half2*>(&v.z);
            __half2 h3 = *reinterpret_cast<__half2*>(&v.w);
            float2 f0 = __half22float2(h0);
            float2 f1 = __half22float2(h1);
            float2 f2 = __half22float2(h2);
            float2 f3 = __half22float2(h3);
            a[0] = fmaf(w, f0.x, a[0]); a[1] = fmaf(w, f0.y, a[1]);
            a[2] = fmaf(w, f1.x, a[2]); a[3] = fmaf(w, f1.y, a[3]);
            a[4] = fmaf(w, f2.x, a[4]); a[5] = fmaf(w, f2.y, a[5]);
            a[6] = fmaf(w, f3.x, a[6]); a[7] = fmaf(w, f3.y, a[7]);
        }
    }
    // reduce across the 4 edge slots; all lanes end with full sums for their 8 dims
    #pragma unroll
    for (int i = 0; i < 8; i++) {
        a[i] += __shfl_xor_sync(0xffffffffu, a[i], 8);
        a[i] += __shfl_xor_sync(0xffffffffu, a[i], 16);
    }

    size_t accBase = (size_t)warp * 16;   // float4 units
    if (slot == 1) {
        // dims [8*sub .. 8*sub+3]
        float4* accp = reinterpret_cast<float4*>(g_acc);
        float4 c = accp[accBase + 2 * sub];
        c.x += a[0]; c.y += a[1]; c.z += a[2]; c.w += a[3];
        accp[accBase + 2 * sub] = c;
    } else if (slot == 2) {
        // dims [8*sub+4 .. 8*sub+7]
        float4* accp = reinterpret_cast<float4*>(g_acc);
        float4 c = accp[accBase + 2 * sub + 1];
        c.x += a[4]; c.y += a[5]; c.z += a[6]; c.w += a[7];
        accp[accBase + 2 * sub + 1] = c;
    } else if (slot == 0 && !last) {
        __half2 h0 = __floats2half2_rn(a[0], a[1]);
        __half2 h1 = __floats2half2_rn(a[2], a[3]);
        __half2 h2 = __floats2half2_rn(a[4], a[5]);
        __half2 h3 = __floats2half2_rn(a[6], a[7]);
        uint4 o;
        o.x = *reinterpret_cast<unsigned int*>(&h0);
        o.y = *reinterpret_cast<unsigned int*>(&h1);
        o.z = *reinterpret_cast<unsigned int*>(&h2);
        o.w = *reinterpret_cast<unsigned int*>(&h3);
        xout[(size_t)warp * 8 + sub] = o;
    }
}

// out = l2norm(acc / 4); trailing scalar align_loss = 0
__global__ void __launch_bounds__(256) final_kernel(float* __restrict__ out) {
    int t = blockIdx.x * blockDim.x + threadIdx.x;
    int node = t >> 4;
    int sub  = t & 15;
    if (node >= NNODE) return;

    size_t o = (size_t)node * 16 + sub;
    float4 v = reinterpret_cast<const float4*>(g_acc)[o];
    v.x *= 0.25f; v.y *= 0.25f; v.z *= 0.25f; v.w *= 0.25f;
    float ss = v.x * v.x + v.y * v.y + v.z * v.z + v.w * v.w;
    #pragma unroll
    for (int oo = 8; oo > 0; oo >>= 1) ss += __shfl_xor_sync(0xffffffffu, ss, oo);
    float inv = 1.f / fmaxf(sqrtf(ss), 1e-12f);
    v.x *= inv; v.y *= inv; v.z *= inv; v.w *= inv;
    reinterpret_cast<float4*>(out)[o] = v;

    if (blockIdx.x == 0 && threadIdx.x == 0) out[(size_t)NNODE * DIM] = 0.f;
}

// ---------------- launcher ----------------
extern "C" void kernel_launch(void* const* d_in, const int* in_sizes, int n_in,
                              void* d_out, int out_size) {
    const float* uemb  = (const float*)d_in[0];   // user_emb_w      [100000,64]
    const float* audio = (const float*)d_in[1];   // item_audio_emb  [50000,64]
    const float* art   = (const float*)d_in[2];   // artist_emb_w    [20000,64]
    const float* alb   = (const float*)d_in[3];   // album_emb_w     [40000,64]
    const float* w1    = (const float*)d_in[4];   // mlp_w1 [8,32]
    const float* b1    = (const float*)d_in[5];   // mlp_b1 [32]
    const float* w2    = (const float*)d_in[6];   // mlp_w2 [32,1]
    const float* b2    = (const float*)d_in[7];   // mlp_b2 [1]
    const float* ef    = (const float*)d_in[8];   // edge_features [E,8]
    const int*   eidx  = (const int*)  d_in[9];   // edge_index [2,E]
    const int*   aid   = (const int*)  d_in[10];  // artist_ids [50000]
    const int*   bid   = (const int*)  d_in[11];  // album_ids  [50000]
    float* out = (float*)d_out;

    const int edgeBlocks = (NEDGE + 255) / 256;
    const int nodeBlocks = (NNODE + 255) / 256;
    const int warpBlocks = (NNODE * 32 + 255) / 256;   // one warp per node
    const int vecBlocks  = (NNODE * 16 + 255) / 256;   // 16 lanes per node

    zero_kernel   <<<nodeBlocks, 256>>>();
    mlp_kernel    <<<edgeBlocks, 256>>>(ef, w1, b1, w2, b2, eidx);
    scan_kernel   <<<1, 1024>>>();
    scatter_kernel<<<edgeBlocks, 256>>>(eidx);
    init_kernel   <<<vecBlocks, 256>>>(uemb, audio, art, alb, aid, bid);
    gather_kernel <<<warpBlocks, 256>>>(0, 0);   // hA -> hB
    gather_kernel <<<warpBlocks, 256>>>(1, 0);   // hB -> hA
    gather_kernel <<<warpBlocks, 256>>>(0, 1);   // hA -> (acc only)
    final_kernel  <<<vecBlocks, 256>>>(out);
}

// round 4
// speedup vs baseline: 3.3862x; 3.1171x over previous
#include <cuda_runtime.h>
#include <cuda_fp16.h>
#include <math.h>
#include <stdint.h>

// ---------------- problem constants ----------------
static constexpr int NUSERS = 100000;
static constexpr int NITEMS = 50000;
static constexpr int NNODE  = 150000;       // NUSERS + NITEMS
static constexpr int NEDGE  = 1200000;      // 2 * 600000
static constexpr int DIM    = 64;
static constexpr int SCANB  = (NNODE + 1023) / 1024;   // 147 scan blocks

// ---------------- device scratch (static; no runtime alloc) ----------------
__device__ float  g_edge_w[NEDGE];
__device__ int2   g_edge[NEDGE];            // {src, __float_as_int(norm_w)}
__device__ float  g_wdeg[NNODE];
__device__ float  g_dinv[NNODE];
__device__ int    g_cnt[NNODE];
__device__ int    g_rowptr[NNODE + 1];
__device__ int    g_cursor[NNODE];
__device__ int    g_bsum[SCANB];
__device__ int    g_boff[SCANB];
__device__ __half g_x0[(size_t)NNODE * DIM];
__device__ __half g_x1[(size_t)NNODE * DIM];
__device__ __half g_x2[(size_t)NNODE * DIM];
__device__ __half g_x3[(size_t)NNODE * DIM];
__device__ __half* const g_xptr[4] = {g_x0, g_x1, g_x2, g_x3};

// ---------------- kernels ----------------

// x0 = [ l2norm(user_emb) ; l2norm(0.3*audio + 0.44*(artist+album)) ]  (fp16)
// 16 lanes per node, float4 per lane.
__global__ void __launch_bounds__(256) init_kernel(const float* __restrict__ uemb,
                            const float* __restrict__ audio,
                            const float* __restrict__ art,
                            const float* __restrict__ alb,
                            const int*   __restrict__ aid,
                            const int*   __restrict__ bid) {
    int t = blockIdx.x * blockDim.x + threadIdx.x;
    int node = t >> 4;
    int sub  = t & 15;
    if (node >= NNODE) return;

    float4 v;
    if (node < NUSERS) {
        v = __ldg(reinterpret_cast<const float4*>(uemb) + (size_t)node * 16 + sub);
    } else {
        int i = node - NUSERS;
        int a = __ldg(&aid[i]);
        int b = __ldg(&bid[i]);
        float4 pa = __ldg(reinterpret_cast<const float4*>(audio) + (size_t)i * 16 + sub);
        float4 pr = __ldg(reinterpret_cast<const float4*>(art)   + (size_t)a * 16 + sub);
        float4 pl = __ldg(reinterpret_cast<const float4*>(alb)   + (size_t)b * 16 + sub);
        v.x = pa.x * 0.3f + (pr.x + pl.x) * 0.44f;
        v.y = pa.y * 0.3f + (pr.y + pl.y) * 0.44f;
        v.z = pa.z * 0.3f + (pr.z + pl.z) * 0.44f;
        v.w = pa.w * 0.3f + (pr.w + pl.w) * 0.44f;
    }
    float ss = v.x * v.x + v.y * v.y + v.z * v.z + v.w * v.w;
    #pragma unroll
    for (int o = 8; o > 0; o >>= 1) ss += __shfl_xor_sync(0xffffffffu, ss, o);
    float inv = 1.f / fmaxf(sqrtf(ss), 1e-12f);

    __half2 h0 = __floats2half2_rn(v.x * inv, v.y * inv);
    __half2 h1 = __floats2half2_rn(v.z * inv, v.w * inv);
    uint2 hv;
    hv.x = *reinterpret_cast<unsigned int*>(&h0);
    hv.y = *reinterpret_cast<unsigned int*>(&h1);
    reinterpret_cast<uint2*>(g_x0)[(size_t)node * 16 + sub] = hv;
}

__global__ void zero_kernel() {
    int i = blockIdx.x * blockDim.x + threadIdx.x;
    if (i < NNODE) { g_wdeg[i] = 0.f; g_cnt[i] = 0; }
}

// edge gate MLP: sigmoid(relu(f @ W1 + b1) @ w2 + b2); histogram weighted degree + count
__global__ void mlp_kernel(const float* __restrict__ ef,
                           const float* __restrict__ w1,
                           const float* __restrict__ b1,
                           const float* __restrict__ w2,
                           const float* __restrict__ b2,
                           const int*   __restrict__ eidx) {
    __shared__ float sW1[8 * 32];
    __shared__ float sB1[32];
    __shared__ float sW2[32];
    __shared__ float sB2;
    int t = threadIdx.x;
    if (t < 256) sW1[t] = w1[t];
    if (t < 32)  { sB1[t] = b1[t]; sW2[t] = w2[t]; }
    if (t == 0)  sB2 = b2[0];
    __syncthreads();

    int e = blockIdx.x * blockDim.x + t;
    if (e >= NEDGE) return;

    const float4* fp = reinterpret_cast<const float4*>(ef + (size_t)e * 8);
    float4 fa = fp[0];
    float4 fb = fp[1];
    float f[8] = {fa.x, fa.y, fa.z, fa.w, fb.x, fb.y, fb.z, fb.w};

    float out = sB2;
    #pragma unroll
    for (int j = 0; j < 32; j++) {
        float h = sB1[j];
        #pragma unroll
        for (int i = 0; i < 8; i++) h = fmaf(f[i], sW1[i * 32 + j], h);
        h = fmaxf(h, 0.f);
        out = fmaf(h, sW2[j], out);
    }
    float w = 1.f / (1.f + expf(-out));

    g_edge_w[e] = w;
    int c = eidx[NEDGE + e];          // edge_index[1][e]
    atomicAdd(&g_wdeg[c], w);
    atomicAdd(&g_cnt[c], 1);
}

// distributed scan phase 1: per-block sums of g_cnt
__global__ void __launch_bounds__(1024) scan1_kernel() {
    __shared__ int sh[1024];
    int n = blockIdx.x * 1024 + threadIdx.x;
    int s = (n < NNODE) ? g_cnt[n] : 0;
    sh[threadIdx.x] = s;
    __syncthreads();
    for (int off = 512; off > 0; off >>= 1) {
        if (threadIdx.x < off) sh[threadIdx.x] += sh[threadIdx.x + off];
        __syncthreads();
    }
    if (threadIdx.x == 0) g_bsum[blockIdx.x] = sh[0];
}

// phase 2: exclusive scan of 147 block sums (one small block)
__global__ void __launch_bounds__(256) scan2_kernel() {
    __shared__ int sh[256];
    int t = threadIdx.x;
    sh[t] = (t < SCANB) ? g_bsum[t] : 0;
    __syncthreads();
    for (int off = 1; off < 256; off <<= 1) {
        int v = (t >= off) ? sh[t - off] : 0;
        __syncthreads();
        sh[t] += v;
        __syncthreads();
    }
    if (t < SCANB) g_boff[t] = sh[t] - g_bsum[t];   // exclusive
    if (t == 0) g_rowptr[NNODE] = NEDGE;
}

// phase 3: block-local exclusive scan + write rowptr/cursor; also dinv
__global__ void __launch_bounds__(1024) scan3_kernel() {
    __shared__ int sh[1024];
    int t = threadIdx.x;
    int n = blockIdx.x * 1024 + t;
    int c = (n < NNODE) ? g_cnt[n] : 0;
    sh[t] = c;
    __syncthreads();
    for (int off = 1; off < 1024; off <<= 1) {
        int v = (t >= off) ? sh[t - off] : 0;
        __syncthreads();
        sh[t] += v;
        __syncthreads();
    }
    if (n < NNODE) {
        int p = g_boff[blockIdx.x] + sh[t] - c;   // global exclusive prefix
        g_rowptr[n] = p;
        g_cursor[n] = p;
        float dg = g_wdeg[n];
        g_dinv[n] = (dg > 0.f) ? rsqrtf(dg) : 0.f;
    }
}

// bucket edges by destination; store {src, pre-normalized weight}
__global__ void scatter_kernel(const int* __restrict__ eidx) {
    int e = blockIdx.x * blockDim.x + threadIdx.x;
    if (e >= NEDGE) return;
    int r = eidx[e];
    int c = eidx[NEDGE + e];
    float w = g_dinv[r] * g_edge_w[e] * g_dinv[c];
    int p = atomicAdd(&g_cursor[c], 1);
    g_edge[p] = make_int2(r, __float_as_int(w));
}

// one propagation layer: x[l+1][n] = sum_{e in CSR[n]} w_e * x[l][src_e]
// warp = 1 node, 4 edges per iteration (8 lanes per edge, uint4 = 8 halves),
// next-iteration edge meta prefetched to break the meta->x dependent chain.
__global__ void __launch_bounds__(256) gather_kernel(int layer) {
    const uint4* __restrict__ xin  = reinterpret_cast<const uint4*>(g_xptr[layer]);
    uint4*       __restrict__ xout = reinterpret_cast<uint4*>(g_xptr[layer + 1]);

    int warp = (blockIdx.x * blockDim.x + threadIdx.x) >> 5;
    int lane = threadIdx.x & 31;
    if (warp >= NNODE) return;
    int slot = lane >> 3;     // 0..3 : which edge of the group of 4
    int sub  = lane & 7;      // 0..7 : which 16B chunk of the 128B row

    int beg = g_rowptr[warp];
    int end = g_rowptr[warp + 1];

    float a[8] = {0.f, 0.f, 0.f, 0.f, 0.f, 0.f, 0.f, 0.f};
    int e = beg + slot;
    int2 m = (e < end) ? __ldg(&g_edge[e]) : make_int2(0, 0);   // w=0 for idle slots
    while (e < end) {
        int2 cur = m;
        int en = e + 4;
        if (en < end) m = __ldg(&g_edge[en]);      // prefetch next meta
        else          m = make_int2(0, 0);
        float w = __int_as_float(cur.y);
        uint4 v = __ldg(xin + (size_t)cur.x * 8 + sub);
        __half2 h0 = *reinterpret_cast<__half2*>(&v.x);
        __half2 h1 = *reinterpret_cast<__half2*>(&v.y);
        __half2 h2 = *reinterpret_cast<__half2*>(&v.z);
        __half2 h3 = *reinterpret_cast<__half2*>(&v.w);
        float2 f0 = __half22float2(h0);
        float2 f1 = __half22float2(h1);
        float2 f2 = __half22float2(h2);
        float2 f3 = __half22float2(h3);
        a[0] = fmaf(w, f0.x, a[0]); a[1] = fmaf(w, f0.y, a[1]);
        a[2] = fmaf(w, f1.x, a[2]); a[3] = fmaf(w, f1.y, a[3]);
        a[4] = fmaf(w, f2.x, a[4]); a[5] = fmaf(w, f2.y, a[5]);
        a[6] = fmaf(w, f3.x, a[6]); a[7] = fmaf(w, f3.y, a[7]);
        e = en;
    }
    // reduce across the 4 edge slots
    #pragma unroll
    for (int i = 0; i < 8; i++) {
        a[i] += __shfl_xor_sync(0xffffffffu, a[i], 8);
        a[i] += __shfl_xor_sync(0xffffffffu, a[i], 16);
    }

    if (slot == 0) {
        __half2 h0 = __floats2half2_rn(a[0], a[1]);
        __half2 h1 = __floats2half2_rn(a[2], a[3]);
        __half2 h2 = __floats2half2_rn(a[4], a[5]);
        __half2 h3 = __floats2half2_rn(a[6], a[7]);
        uint4 o;
        o.x = *reinterpret_cast<unsigned int*>(&h0);
        o.y = *reinterpret_cast<unsigned int*>(&h1);
        o.z = *reinterpret_cast<unsigned int*>(&h2);
        o.w = *reinterpret_cast<unsigned int*>(&h3);
        xout[(size_t)warp * 8 + sub] = o;
    }
}

// out = l2norm((x0+x1+x2+x3) / 4); trailing scalar align_loss = 0
// 8 lanes per node, 8 dims per lane.
__global__ void __launch_bounds__(256) final_kernel(float* __restrict__ out) {
    int t = blockIdx.x * blockDim.x + threadIdx.x;
    int node = t >> 3;
    int sub  = t & 7;
    if (node >= NNODE) return;

    size_t o = (size_t)node * 8 + sub;
    float a[8] = {0.f, 0.f, 0.f, 0.f, 0.f, 0.f, 0.f, 0.f};
    #pragma unroll
    for (int l = 0; l < 4; l++) {
        uint4 v = reinterpret_cast<const uint4*>(g_xptr[l])[o];
        float2 f0 = __half22float2(*reinterpret_cast<__half2*>(&v.x));
        float2 f1 = __half22float2(*reinterpret_cast<__half2*>(&v.y));
        float2 f2 = __half22float2(*reinterpret_cast<__half2*>(&v.z));
        float2 f3 = __half22float2(*reinterpret_cast<__half2*>(&v.w));
        a[0] += f0.x; a[1] += f0.y; a[2] += f1.x; a[3] += f1.y;
        a[4] += f2.x; a[5] += f2.y; a[6] += f3.x; a[7] += f3.y;
    }
    float ss = 0.f;
    #pragma unroll
    for (int i = 0; i < 8; i++) { a[i] *= 0.25f; ss = fmaf(a[i], a[i], ss); }
    #pragma unroll
    for (int oo = 4; oo > 0; oo >>= 1) ss += __shfl_xor_sync(0xffffffffu, ss, oo);
    float inv = 1.f / fmaxf(sqrtf(ss), 1e-12f);

    float4* op = reinterpret_cast<float4*>(out);
    float4 o0 = make_float4(a[0] * inv, a[1] * inv, a[2] * inv, a[3] * inv);
    float4 o1 = make_float4(a[4] * inv, a[5] * inv, a[6] * inv, a[7] * inv);
    op[(size_t)node * 16 + 2 * sub]     = o0;
    op[(size_t)node * 16 + 2 * sub + 1] = o1;

    if (blockIdx.x == 0 && threadIdx.x == 0) out[(size_t)NNODE * DIM] = 0.f;
}

// ---------------- launcher ----------------
extern "C" void kernel_launch(void* const* d_in, const int* in_sizes, int n_in,
                              void* d_out, int out_size) {
    const float* uemb  = (const float*)d_in[0];   // user_emb_w      [100000,64]
    const float* audio = (const float*)d_in[1];   // item_audio_emb  [50000,64]
    const float* art   = (const float*)d_in[2];   // artist_emb_w    [20000,64]
    const float* alb   = (const float*)d_in[3];   // album_emb_w     [40000,64]
    const float* w1    = (const float*)d_in[4];   // mlp_w1 [8,32]
    const float* b1    = (const float*)d_in[5];   // mlp_b1 [32]
    const float* w2    = (const float*)d_in[6];   // mlp_w2 [32,1]
    const float* b2    = (const float*)d_in[7];   // mlp_b2 [1]
    const float* ef    = (const float*)d_in[8];   // edge_features [E,8]
    const int*   eidx  = (const int*)  d_in[9];   // edge_index [2,E]
    const int*   aid   = (const int*)  d_in[10];  // artist_ids [50000]
    const int*   bid   = (const int*)  d_in[11];  // album_ids  [50000]
    float* out = (float*)d_out;

    const int edgeBlocks = (NEDGE + 255) / 256;
    const int nodeBlocks = (NNODE + 255) / 256;
    const int warpBlocks = (NNODE * 32 + 255) / 256;   // one warp per node
    const int vecBlocks  = (NNODE * 16 + 255) / 256;   // 16 lanes per node
    const int octBlocks  = (NNODE * 8  + 255) / 256;   // 8 lanes per node

    init_kernel   <<<vecBlocks, 256>>>(uemb, audio, art, alb, aid, bid);
    zero_kernel   <<<nodeBlocks, 256>>>();
    mlp_kernel    <<<edgeBlocks, 256>>>(ef, w1, b1, w2, b2, eidx);
    scan1_kernel  <<<SCANB, 1024>>>();
    scan2_kernel  <<<1, 256>>>();
    scan3_kernel  <<<SCANB, 1024>>>();
    scatter_kernel<<<edgeBlocks, 256>>>(eidx);
    gather_kernel <<<warpBlocks, 256>>>(0);   // x0 -> x1
    gather_kernel <<<warpBlocks, 256>>>(1);   // x1 -> x2
    gather_kernel <<<warpBlocks, 256>>>(2);   // x2 -> x3
    final_kernel  <<<octBlocks, 256>>>(out);
}

// round 5
// speedup vs baseline: 3.5648x; 1.0527x over previous
#include <cuda_runtime.h>
#include <cuda_fp16.h>
#include <math.h>
#include <stdint.h>

// ---------------- problem constants ----------------
static constexpr int NUSERS = 100000;
static constexpr int NITEMS = 50000;
static constexpr int NNODE  = 150000;       // NUSERS + NITEMS
static constexpr int NEDGE  = 1200000;      // 2 * 600000
static constexpr int DIM    = 64;
static constexpr int SCANB  = (NNODE + 1023) / 1024;   // 147 scan blocks

// ---------------- device scratch (static; no runtime alloc) ----------------
__device__ float  g_edge_w[NEDGE];
__device__ int2   g_edge[NEDGE];            // {src, __float_as_int(edge_w * dinv[src])}
__device__ float  g_wdeg[NNODE];
__device__ float  g_dinv[NNODE];
__device__ int    g_cnt[NNODE];
__device__ int    g_rowptr[NNODE + 1];
__device__ int    g_cursor[NNODE];
__device__ int    g_bsum[SCANB];
__device__ __half g_x0[(size_t)NNODE * DIM];
__device__ __half g_x1[(size_t)NNODE * DIM];
__device__ __half g_x2[(size_t)NNODE * DIM];
__device__ __half g_x3[(size_t)NNODE * DIM];
__device__ __half* const g_xptr[4] = {g_x0, g_x1, g_x2, g_x3};

// ---------------- kernels ----------------

// x0 = [ l2norm(user_emb) ; l2norm(0.3*audio + 0.44*(artist+album)) ]  (fp16)
// 16 lanes per node, float4 per lane. Also zeroes g_wdeg / g_cnt (fused).
__global__ void __launch_bounds__(256) init_kernel(const float* __restrict__ uemb,
                            const float* __restrict__ audio,
                            const float* __restrict__ art,
                            const float* __restrict__ alb,
                            const int*   __restrict__ aid,
                            const int*   __restrict__ bid) {
    int t = blockIdx.x * blockDim.x + threadIdx.x;
    if (t < NNODE) { g_wdeg[t] = 0.f; g_cnt[t] = 0; }

    int node = t >> 4;
    int sub  = t & 15;
    if (node >= NNODE) return;

    float4 v;
    if (node < NUSERS) {
        v = __ldg(reinterpret_cast<const float4*>(uemb) + (size_t)node * 16 + sub);
    } else {
        int i = node - NUSERS;
        int a = __ldg(&aid[i]);
        int b = __ldg(&bid[i]);
        float4 pa = __ldg(reinterpret_cast<const float4*>(audio) + (size_t)i * 16 + sub);
        float4 pr = __ldg(reinterpret_cast<const float4*>(art)   + (size_t)a * 16 + sub);
        float4 pl = __ldg(reinterpret_cast<const float4*>(alb)   + (size_t)b * 16 + sub);
        v.x = pa.x * 0.3f + (pr.x + pl.x) * 0.44f;
        v.y = pa.y * 0.3f + (pr.y + pl.y) * 0.44f;
        v.z = pa.z * 0.3f + (pr.z + pl.z) * 0.44f;
        v.w = pa.w * 0.3f + (pr.w + pl.w) * 0.44f;
    }
    float ss = v.x * v.x + v.y * v.y + v.z * v.z + v.w * v.w;
    #pragma unroll
    for (int o = 8; o > 0; o >>= 1) ss += __shfl_xor_sync(0xffffffffu, ss, o);
    float inv = 1.f / fmaxf(sqrtf(ss), 1e-12f);

    __half2 h0 = __floats2half2_rn(v.x * inv, v.y * inv);
    __half2 h1 = __floats2half2_rn(v.z * inv, v.w * inv);
    uint2 hv;
    hv.x = *reinterpret_cast<unsigned int*>(&h0);
    hv.y = *reinterpret_cast<unsigned int*>(&h1);
    reinterpret_cast<uint2*>(g_x0)[(size_t)node * 16 + sub] = hv;
}

// edge gate MLP: sigmoid(relu(f @ W1 + b1) @ w2 + b2); histogram weighted degree + count
__global__ void mlp_kernel(const float* __restrict__ ef,
                           const float* __restrict__ w1,
                           const float* __restrict__ b1,
                           const float* __restrict__ w2,
                           const float* __restrict__ b2,
                           const int*   __restrict__ eidx) {
    __shared__ float sW1[8 * 32];
    __shared__ float sB1[32];
    __shared__ float sW2[32];
    __shared__ float sB2;
    int t = threadIdx.x;
    if (t < 256) sW1[t] = w1[t];
    if (t < 32)  { sB1[t] = b1[t]; sW2[t] = w2[t]; }
    if (t == 0)  sB2 = b2[0];
    __syncthreads();

    int e = blockIdx.x * blockDim.x + t;
    if (e >= NEDGE) return;

    const float4* fp = reinterpret_cast<const float4*>(ef + (size_t)e * 8);
    float4 fa = fp[0];
    float4 fb = fp[1];
    float f[8] = {fa.x, fa.y, fa.z, fa.w, fb.x, fb.y, fb.z, fb.w};

    float out = sB2;
    #pragma unroll
    for (int j = 0; j < 32; j++) {
        float h = sB1[j];
        #pragma unroll
        for (int i = 0; i < 8; i++) h = fmaf(f[i], sW1[i * 32 + j], h);
        h = fmaxf(h, 0.f);
        out = fmaf(h, sW2[j], out);
    }
    float w = 1.f / (1.f + expf(-out));

    g_edge_w[e] = w;
    int c = eidx[NEDGE + e];          // edge_index[1][e]
    atomicAdd(&g_wdeg[c], w);
    atomicAdd(&g_cnt[c], 1);
}

// scan phase 1: per-block sums of g_cnt
__global__ void __launch_bounds__(1024) scan1_kernel() {
    __shared__ int sh[1024];
    int n = blockIdx.x * 1024 + threadIdx.x;
    int s = (n < NNODE) ? g_cnt[n] : 0;
    sh[threadIdx.x] = s;
    __syncthreads();
    for (int off = 512; off > 0; off >>= 1) {
        if (threadIdx.x < off) sh[threadIdx.x] += sh[threadIdx.x + off];
        __syncthreads();
    }
    if (threadIdx.x == 0) g_bsum[blockIdx.x] = sh[0];
}

// scan phase 2+3 fused: every block scans the 147 block sums redundantly in
// shared, then does its local exclusive scan and writes rowptr/cursor/dinv.
__global__ void __launch_bounds__(1024) scan3_kernel() {
    __shared__ int sums[256];
    __shared__ int sh[1024];
    int t = threadIdx.x;
    if (t < 256) sums[t] = (t < SCANB) ? g_bsum[t] : 0;
    __syncthreads();
    for (int off = 1; off < 256; off <<= 1) {
        int v = (t < 256 && t >= off) ? sums[t - off] : 0;
        __syncthreads();
        if (t < 256) sums[t] += v;
        __syncthreads();
    }
    int blockOff = (blockIdx.x == 0) ? 0 : sums[blockIdx.x - 1];

    int n = blockIdx.x * 1024 + t;
    int c = (n < NNODE) ? g_cnt[n] : 0;
    sh[t] = c;
    __syncthreads();
    for (int off = 1; off < 1024; off <<= 1) {
        int v = (t >= off) ? sh[t - off] : 0;
        __syncthreads();
        sh[t] += v;
        __syncthreads();
    }
    if (n < NNODE) {
        int p = blockOff + sh[t] - c;   // global exclusive prefix
        g_rowptr[n] = p;
        g_cursor[n] = p;
        float dg = g_wdeg[n];
        g_dinv[n] = (dg > 0.f) ? rsqrtf(dg) : 0.f;
    }
    if (blockIdx.x == 0 && t == 0) g_rowptr[NNODE] = NEDGE;
}

// bucket edges by destination; store {src, edge_w * dinv[src]}; 2 edges/thread
__global__ void __launch_bounds__(256) scatter_kernel(const int* __restrict__ eidx) {
    int e = (blockIdx.x * blockDim.x + threadIdx.x) * 2;
    if (e >= NEDGE) return;
    int2   r2 = __ldg(reinterpret_cast<const int2*>(eidx + e));           // rows
    int2   c2 = __ldg(reinterpret_cast<const int2*>(eidx + NEDGE + e));   // cols
    float2 w2 = __ldg(reinterpret_cast<const float2*>(g_edge_w + e));

    float wa = w2.x * __ldg(&g_dinv[r2.x]);
    int pa = atomicAdd(&g_cursor[c2.x], 1);
    g_edge[pa] = make_int2(r2.x, __float_as_int(wa));

    float wb = w2.y * __ldg(&g_dinv[r2.y]);
    int pb = atomicAdd(&g_cursor[c2.y], 1);
    g_edge[pb] = make_int2(r2.y, __float_as_int(wb));
}

// one propagation layer: x[l+1][n] = dinv[n] * sum_e w'_e * x[l][src_e]
// warp = 1 node, 8 edges per iteration (two groups of 4; 8 lanes per edge,
// uint4 = 8 halves; row = 128B = one cache line).
__global__ void __launch_bounds__(256) gather_kernel(int layer) {
    const uint4* __restrict__ xin  = reinterpret_cast<const uint4*>(g_xptr[layer]);
    uint4*       __restrict__ xout = reinterpret_cast<uint4*>(g_xptr[layer + 1]);

    int warp = (blockIdx.x * blockDim.x + threadIdx.x) >> 5;
    int lane = threadIdx.x & 31;
    if (warp >= NNODE) return;
    int slot = lane >> 3;     // 0..3 : which edge within a group of 4
    int sub  = lane & 7;      // 0..7 : which 16B chunk of the 128B row

    int beg = g_rowptr[warp];
    int end = g_rowptr[warp + 1];

    float a[8] = {0.f, 0.f, 0.f, 0.f, 0.f, 0.f, 0.f, 0.f};
    for (int e = beg; e < end; e += 8) {
        int e0 = e + slot;
        int e1 = e + 4 + slot;
        int2 m0 = (e0 < end) ? __ldg(&g_edge[e0]) : make_int2(0, 0);
        int2 m1 = (e1 < end) ? __ldg(&g_edge[e1]) : make_int2(0, 0);
        float w0 = __int_as_float(m0.y);
        float w1 = __int_as_float(m1.y);
        uint4 v0 = __ldg(xin + (size_t)m0.x * 8 + sub);
        uint4 v1 = __ldg(xin + (size_t)m1.x * 8 + sub);

        float2 f0 = __half22float2(*reinterpret_cast<__half2*>(&v0.x));
        float2 f1 = __half22float2(*reinterpret_cast<__half2*>(&v0.y));
        float2 f2 = __half22float2(*reinterpret_cast<__half2*>(&v0.z));
        float2 f3 = __half22float2(*reinterpret_cast<__half2*>(&v0.w));
        a[0] = fmaf(w0, f0.x, a[0]); a[1] = fmaf(w0, f0.y, a[1]);
        a[2] = fmaf(w0, f1.x, a[2]); a[3] = fmaf(w0, f1.y, a[3]);
        a[4] = fmaf(w0, f2.x, a[4]); a[5] = fmaf(w0, f2.y, a[5]);
        a[6] = fmaf(w0, f3.x, a[6]); a[7] = fmaf(w0, f3.y, a[7]);

        float2 g0 = __half22float2(*reinterpret_cast<__half2*>(&v1.x));
        float2 g1 = __half22float2(*reinterpret_cast<__half2*>(&v1.y));
        float2 g2 = __half22float2(*reinterpret_cast<__half2*>(&v1.z));
        float2 g3 = __half22float2(*reinterpret_cast<__half2*>(&v1.w));
        a[0] = fmaf(w1, g0.x, a[0]); a[1] = fmaf(w1, g0.y, a[1]);
        a[2] = fmaf(w1, g1.x, a[2]); a[3] = fmaf(w1, g1.y, a[3]);
        a[4] = fmaf(w1, g2.x, a[4]); a[5] = fmaf(w1, g2.y, a[5]);
        a[6] = fmaf(w1, g3.x, a[6]); a[7] = fmaf(w1, g3.y, a[7]);
    }
    // reduce across the 4 edge slots
    #pragma unroll
    for (int i = 0; i < 8; i++) {
        a[i] += __shfl_xor_sync(0xffffffffu, a[i], 8);
        a[i] += __shfl_xor_sync(0xffffffffu, a[i], 16);
    }

    if (slot == 0) {
        float dv = __ldg(&g_dinv[warp]);   // dinv[dst] applied once per node
        __half2 h0 = __floats2half2_rn(a[0] * dv, a[1] * dv);
        __half2 h1 = __floats2half2_rn(a[2] * dv, a[3] * dv);
        __half2 h2 = __floats2half2_rn(a[4] * dv, a[5] * dv);
        __half2 h3 = __floats2half2_rn(a[6] * dv, a[7] * dv);
        uint4 o;
        o.x = *reinterpret_cast<unsigned int*>(&h0);
        o.y = *reinterpret_cast<unsigned int*>(&h1);
        o.z = *reinterpret_cast<unsigned int*>(&h2);
        o.w = *reinterpret_cast<unsigned int*>(&h3);
        xout[(size_t)warp * 8 + sub] = o;
    }
}

// out = l2norm((x0+x1+x2+x3) / 4); trailing scalar align_loss = 0
// 8 lanes per node, 8 dims per lane.
__global__ void __launch_bounds__(256) final_kernel(float* __restrict__ out) {
    int t = blockIdx.x * blockDim.x + threadIdx.x;
    int node = t >> 3;
    int sub  = t & 7;
    if (node >= NNODE) return;

    size_t o = (size_t)node * 8 + sub;
    float a[8] = {0.f, 0.f, 0.f, 0.f, 0.f, 0.f, 0.f, 0.f};
    #pragma unroll
    for (int l = 0; l < 4; l++) {
        uint4 v = reinterpret_cast<const uint4*>(g_xptr[l])[o];
        float2 f0 = __half22float2(*reinterpret_cast<__half2*>(&v.x));
        float2 f1 = __half22float2(*reinterpret_cast<__half2*>(&v.y));
        float2 f2 = __half22float2(*reinterpret_cast<__half2*>(&v.z));
        float2 f3 = __half22float2(*reinterpret_cast<__half2*>(&v.w));
        a[0] += f0.x; a[1] += f0.y; a[2] += f1.x; a[3] += f1.y;
        a[4] += f2.x; a[5] += f2.y; a[6] += f3.x; a[7] += f3.y;
    }
    float ss = 0.f;
    #pragma unroll
    for (int i = 0; i < 8; i++) { a[i] *= 0.25f; ss = fmaf(a[i], a[i], ss); }
    #pragma unroll
    for (int oo = 4; oo > 0; oo >>= 1) ss += __shfl_xor_sync(0xffffffffu, ss, oo);
    float inv = 1.f / fmaxf(sqrtf(ss), 1e-12f);

    float4* op = reinterpret_cast<float4*>(out);
    op[(size_t)node * 16 + 2 * sub]     = make_float4(a[0] * inv, a[1] * inv, a[2] * inv, a[3] * inv);
    op[(size_t)node * 16 + 2 * sub + 1] = make_float4(a[4] * inv, a[5] * inv, a[6] * inv, a[7] * inv);

    if (blockIdx.x == 0 && threadIdx.x == 0) out[(size_t)NNODE * DIM] = 0.f;
}

// ---------------- launcher ----------------
extern "C" void kernel_launch(void* const* d_in, const int* in_sizes, int n_in,
                              void* d_out, int out_size) {
    const float* uemb  = (const float*)d_in[0];
    const float* audio = (const float*)d_in[1];
    const float* art   = (const float*)d_in[2];
    const float* alb   = (const float*)d_in[3];
    const float* w1    = (const float*)d_in[4];
    const float* b1    = (const float*)d_in[5];
    const float* w2    = (const float*)d_in[6];
    const float* b2    = (const float*)d_in[7];
    const float* ef    = (const float*)d_in[8];
    const int*   eidx  = (const int*)  d_in[9];
    const int*   aid   = (const int*)  d_in[10];
    const int*   bid   = (const int*)  d_in[11];
    float* out = (float*)d_out;

    const int edgeBlocks  = (NEDGE + 255) / 256;
    const int edge2Blocks = (NEDGE / 2 + 255) / 256;
    const int warpBlocks  = (NNODE * 32 + 255) / 256;   // one warp per node
    const int vecBlocks   = (NNODE * 16 + 255) / 256;   // 16 lanes per node
    const int octBlocks   = (NNODE * 8  + 255) / 256;   // 8 lanes per node

    init_kernel   <<<vecBlocks, 256>>>(uemb, audio, art, alb, aid, bid);
    mlp_kernel    <<<edgeBlocks, 256>>>(ef, w1, b1, w2, b2, eidx);
    scan1_kernel  <<<SCANB, 1024>>>();
    scan3_kernel  <<<SCANB, 1024>>>();
    scatter_kernel<<<edge2Blocks, 256>>>(eidx);
    gather_kernel <<<warpBlocks, 256>>>(0);   // x0 -> x1
    gather_kernel <<<warpBlocks, 256>>>(1);   // x1 -> x2
    gather_kernel <<<warpBlocks, 256>>>(2);   // x2 -> x3
    final_kernel  <<<octBlocks, 256>>>(out);
}